// round 5
// baseline (speedup 1.0000x reference)
#include <cuda_runtime.h>

typedef unsigned long long u64;

#define ND 20000
#define NG 20000
#define NC 10000
#define DD 128
#define TT 10
#define BB 4096

// ---------------- scratch (device globals; no allocation allowed) -------------
__device__ float g_E_drug[ND * DD];
__device__ float g_E_gene[NG * DD];
__device__ float g_E_cell[NC * DD];
// XW[lt][b*10+s][384]
__device__ float g_XW[2 * 3 * BB * TT * 384];
// S[lt][b][128]
__device__ float g_S[2 * 3 * BB * DD];

// ---------------- helpers ----------------
__device__ __forceinline__ u64 fma2(u64 a, u64 b, u64 c) {
    u64 d;
    asm("fma.rn.f32x2 %0, %1, %2, %3;" : "=l"(d) : "l"(a), "l"(b), "l"(c));
    return d;
}
__device__ __forceinline__ float2 unpack2(u64 a) {
    unsigned lo, hi;
    asm("mov.b64 {%0, %1}, %2;" : "=r"(lo), "=r"(hi) : "l"(a));
    return make_float2(__uint_as_float(lo), __uint_as_float(hi));
}
__device__ __forceinline__ u64 splat2(float v) {
    u64 d;
    unsigned u = __float_as_uint(v);
    asm("mov.b64 %0, {%1, %1};" : "=l"(d) : "r"(u));
    return d;
}
__device__ __forceinline__ unsigned smem_addr(const void* p) {
    return (unsigned)__cvta_generic_to_shared(p);
}
__device__ __forceinline__ void cp16(unsigned dst, const void* src) {
    asm volatile("cp.async.cg.shared.global [%0], [%1], 16;" :: "r"(dst), "l"(src));
}
__device__ __forceinline__ float sigmf(float x) {
    return __fdividef(1.f, 1.f + __expf(-x));
}
__device__ __forceinline__ float tanh_fast(float x) {
    float ax = fabsf(x);
    float e = __expf(-2.f * ax);
    float r = __fdividef(1.f - e, 1.f + e);
    return copysignf(r, x);
}

// ---------------- 1) table projection: E = F @ W + b ----------------
// 256 threads; 128 rows/block; thread tile = 8 rows x 4 col-pairs.
__global__ __launch_bounds__(256) void proj_kernel(
    const float* __restrict__ F, const float* __restrict__ W,
    const float* __restrict__ bias, int sel, int N, int K)
{
    __shared__ float sW[32 * 128];
    __shared__ u64 sF2[128 * 33];

    float* __restrict__ E = (sel == 0) ? g_E_drug : (sel == 1) ? g_E_gene : g_E_cell;

    int tid = threadIdx.x;
    int cg = tid & 15;
    int rg = tid >> 4;
    int row0 = blockIdx.x * 128;
    int sr  = tid >> 1;
    int skq = (tid & 1) * 16;

    u64 acc[8][4];
#pragma unroll
    for (int i = 0; i < 8; i++)
#pragma unroll
        for (int j = 0; j < 4; j++) acc[i][j] = 0ull;

    int srow = row0 + sr;
    int srr = srow < N ? srow : N - 1;
    const float* frow = F + (size_t)srr * K;

    float4 wreg[4], freg[4];
    {
        const float4* wsrc = (const float4*)W;
#pragma unroll
        for (int i = 0; i < 4; i++) wreg[i] = wsrc[tid + i * 256];
        const float4* fsrc = (const float4*)(frow + skq);
#pragma unroll
        for (int i = 0; i < 4; i++) freg[i] = fsrc[i];
    }

    for (int k0 = 0; k0 < K; k0 += 32) {
        __syncthreads();
#pragma unroll
        for (int i = 0; i < 4; i++) ((float4*)sW)[tid + i * 256] = wreg[i];
#pragma unroll
        for (int i = 0; i < 4; i++) {
            int base = sr * 33 + skq + i * 4;
            sF2[base + 0] = splat2(freg[i].x);
            sF2[base + 1] = splat2(freg[i].y);
            sF2[base + 2] = splat2(freg[i].z);
            sF2[base + 3] = splat2(freg[i].w);
        }
        __syncthreads();
        if (k0 + 32 < K) {
            const float4* wsrc = (const float4*)(W + (size_t)(k0 + 32) * 128);
#pragma unroll
            for (int i = 0; i < 4; i++) wreg[i] = wsrc[tid + i * 256];
            const float4* fsrc = (const float4*)(frow + k0 + 32 + skq);
#pragma unroll
            for (int i = 0; i < 4; i++) freg[i] = fsrc[i];
        }
#pragma unroll 4
        for (int kk = 0; kk < 32; kk++) {
            u64 w[4];
#pragma unroll
            for (int j = 0; j < 4; j++)
                w[j] = *(const u64*)(sW + kk * 128 + 8 * cg + 2 * j);
            u64 x[8];
#pragma unroll
            for (int i = 0; i < 8; i++)
                x[i] = sF2[(rg * 8 + i) * 33 + kk];
#pragma unroll
            for (int i = 0; i < 8; i++)
#pragma unroll
                for (int j = 0; j < 4; j++)
                    acc[i][j] = fma2(x[i], w[j], acc[i][j]);
        }
    }

    float2 b2[4];
#pragma unroll
    for (int j = 0; j < 4; j++) b2[j] = ((const float2*)bias)[cg * 4 + j];
#pragma unroll
    for (int i = 0; i < 8; i++) {
        int row = row0 + rg * 8 + i;
        if (row < N) {
#pragma unroll
            for (int j = 0; j < 4; j++) {
                float2 a = unpack2(acc[i][j]);
                a.x += b2[j].x; a.y += b2[j].y;
                ((float2*)E)[(size_t)row * 64 + cg * 4 + j] = a;
            }
        }
    }
}

// ---------------- 2) XW precompute (512 thr, cp.async double-buffered W) ------
// 64 gathered rows/block; thread tile = 8 rows x 3 col-pairs (cg + j*64).
// W streamed as four 32-k tiles, double buffered via cp.async.
__global__ __launch_bounds__(512) void xw_kernel(
    const float* __restrict__ gruW, const float* __restrict__ gruB,
    const int* __restrict__ nbr_d, const int* __restrict__ nbr_g,
    const int* __restrict__ nbr_c)
{
    extern __shared__ float sm[];
    float* sW  = sm;                       // 2 x (32*384) floats = 96KB
    u64*   sX2 = (u64*)(sm + 24576);       // 64 rows x 128 = 64KB
    int*   sId = (int*)(sX2 + 64 * 128);   // 64

    int tid = threadIdx.x;
    int lt = blockIdx.y;
    int t3 = lt % 3;
    const int* nbr = (t3 == 0) ? nbr_d : (t3 == 1) ? nbr_g : nbr_c;
    const float* Etab = (t3 == 0) ? g_E_drug : (t3 == 1) ? g_E_gene : g_E_cell;
    int grow0 = blockIdx.x * 64;

    const float* Wbase = gruW + (size_t)lt * 49152;

    if (tid < 64) sId[tid] = nbr[grow0 + tid];

    // kick off W tile 0 DMA
    {
        unsigned d = smem_addr(sW);
        const float4* src = (const float4*)Wbase;
#pragma unroll
        for (int i = 0; i < 6; i++)
            cp16(d + (tid + i * 512) * 16, src + tid + i * 512);
        asm volatile("cp.async.commit_group;");
    }
    __syncthreads();   // sId visible

    // stage gathered X (duplicated splats), all 128 k — overlaps tile-0 DMA
    {
        int r = tid >> 3;
        int kq = (tid & 7) * 16;
        int id = sId[r];
        const float4* src = (id >= 0) ? (const float4*)(Etab + (size_t)id * 128 + kq) : 0;
#pragma unroll
        for (int i = 0; i < 4; i++) {
            float4 f = (id >= 0) ? src[i] : make_float4(0.f, 0.f, 0.f, 0.f);
            int base = r * 128 + kq + i * 4;
            sX2[base + 0] = splat2(f.x);
            sX2[base + 1] = splat2(f.y);
            sX2[base + 2] = splat2(f.z);
            sX2[base + 3] = splat2(f.w);
        }
    }

    int cg = tid & 63;       // pairs cg + j*64, j in [0,3)
    int rg = tid >> 6;       // rows rg*8 .. rg*8+7

    u64 acc[8][3];
#pragma unroll
    for (int i = 0; i < 8; i++)
#pragma unroll
        for (int j = 0; j < 3; j++) acc[i][j] = 0ull;

#pragma unroll
    for (int t = 0; t < 4; t++) {
        if (t < 3) {   // prefetch next W tile into alternate buffer
            unsigned d = smem_addr(sW + ((t + 1) & 1) * 12288);
            const float4* src = (const float4*)(Wbase + (t + 1) * 12288);
#pragma unroll
            for (int i = 0; i < 6; i++)
                cp16(d + (tid + i * 512) * 16, src + tid + i * 512);
            asm volatile("cp.async.commit_group;");
            asm volatile("cp.async.wait_group 1;");
        } else {
            asm volatile("cp.async.wait_group 0;");
        }
        __syncthreads();   // tile t visible to all; X staged (t=0)

        const float* wt = sW + (t & 1) * 12288;
#pragma unroll 4
        for (int kk = 0; kk < 32; kk++) {
            u64 x[8];
#pragma unroll
            for (int i = 0; i < 8; i++)
                x[i] = sX2[(rg * 8 + i) * 128 + t * 32 + kk];
            u64 w[3];
#pragma unroll
            for (int j = 0; j < 3; j++)
                w[j] = *(const u64*)(wt + kk * 384 + 2 * (cg + j * 64));
#pragma unroll
            for (int i = 0; i < 8; i++)
#pragma unroll
                for (int j = 0; j < 3; j++)
                    acc[i][j] = fma2(x[i], w[j], acc[i][j]);
        }
        __syncthreads();   // done reading buffer before next DMA overwrites it
    }

    float2 b2[3];
#pragma unroll
    for (int j = 0; j < 3; j++) b2[j] = ((const float2*)(gruB + lt * 384))[cg + j * 64];
#pragma unroll
    for (int i = 0; i < 8; i++) {
        int grow = grow0 + rg * 8 + i;
#pragma unroll
        for (int j = 0; j < 3; j++) {
            float2 a = unpack2(acc[i][j]);
            a.x += b2[j].x; a.y += b2[j].y;
            ((float2*)g_XW)[((size_t)lt * 40960 + grow) * 192 + cg + j * 64] = a;
        }
    }
}

// ---------------- 3) GRU recurrence + masked mean (512 thr) ----------------
// 32 batch rows/block; 64 dim-pairs x 8 row-parts (4 rows each).
// U (192KB) + duplicated H (32KB) in smem; XW gate inputs prefetched to regs.
__global__ __launch_bounds__(512) void gru_kernel(
    const float* __restrict__ gruU,
    const int* __restrict__ nbr_d, const int* __restrict__ nbr_g,
    const int* __restrict__ nbr_c)
{
    extern __shared__ float sm[];
    float*  sU  = sm;                          // 128*384
    float2* sH2 = (float2*)(sm + 49152);       // [32][128] duplicated splats
    float*  sM  = (float*)(sH2 + 32 * 128);    // [32][10]
    float*  sCnt = sM + 320;                   // [32]

    int tid = threadIdx.x;
    int lt = blockIdx.y;
    int t3 = lt % 3;
    const int* nbr = (t3 == 0) ? nbr_d : (t3 == 1) ? nbr_g : nbr_c;
    int b0 = blockIdx.x * 32;

    {
        const float4* src = (const float4*)(gruU + (size_t)lt * 49152);
        float4* dst = (float4*)sU;
#pragma unroll
        for (int i = 0; i < 24; i++) dst[tid + i * 512] = src[tid + i * 512];
    }
    if (tid < 320) {
        int rr = tid / 10, s = tid % 10;
        sM[tid] = (nbr[(size_t)(b0 + rr) * 10 + s] >= 0) ? 1.f : 0.f;
    }
    for (int i = tid; i < 4096; i += 512) sH2[i] = make_float2(0.f, 0.f);
    __syncthreads();
    if (tid < 32) {
        float cnt = 0.f;
        for (int s = 0; s < 10; s++) cnt += sM[tid * 10 + s];
        sCnt[tid] = fmaxf(cnt, 1.f);
    }
    __syncthreads();

    int d2 = tid & 63, rpart = tid >> 6;   // 4 rows per thread
    float2 msum[4];
#pragma unroll
    for (int i = 0; i < 4; i++) msum[i] = make_float2(0.f, 0.f);

    for (int s = 0; s < 10; s++) {
        // prefetch this step's gate inputs (global) — hidden under the GEMM
        float2 pxz[4], pxr[4], pxn[4];
#pragma unroll
        for (int i = 0; i < 4; i++) {
            int bg = b0 + rpart * 4 + i;
            const float* xwb = g_XW + ((size_t)lt * 40960 + (size_t)bg * 10 + s) * 384;
            pxz[i] = *(const float2*)(xwb + 2 * d2);
            pxr[i] = *(const float2*)(xwb + 128 + 2 * d2);
            pxn[i] = *(const float2*)(xwb + 256 + 2 * d2);
        }

        u64 az[4], ar[4], an[4];
#pragma unroll
        for (int i = 0; i < 4; i++) { az[i] = 0ull; ar[i] = 0ull; an[i] = 0ull; }

#pragma unroll 4
        for (int k = 0; k < 128; k++) {
            u64 uz = *(const u64*)(sU + k * 384 + 2 * d2);
            u64 ur = *(const u64*)(sU + k * 384 + 128 + 2 * d2);
            u64 un = *(const u64*)(sU + k * 384 + 256 + 2 * d2);
#pragma unroll
            for (int i = 0; i < 4; i++) {
                u64 hh = *(const u64*)(sH2 + (rpart * 4 + i) * 128 + k);
                az[i] = fma2(hh, uz, az[i]);
                ar[i] = fma2(hh, ur, ar[i]);
                an[i] = fma2(hh, un, an[i]);
            }
        }
        __syncthreads();   // all reads of H done before updates
#pragma unroll
        for (int i = 0; i < 4; i++) {
            int rl = rpart * 4 + i;
            float2 hz = unpack2(az[i]), hr = unpack2(ar[i]), hn = unpack2(an[i]);
            float hox = sH2[rl * 128 + 2 * d2].x;
            float hoy = sH2[rl * 128 + 2 * d2 + 1].x;
            float zx = sigmf(pxz[i].x + hz.x), zy = sigmf(pxz[i].y + hz.y);
            float rx = sigmf(pxr[i].x + hr.x), ry = sigmf(pxr[i].y + hr.y);
            float nx = tanh_fast(pxn[i].x + rx * hn.x);
            float ny = tanh_fast(pxn[i].y + ry * hn.y);
            float hx = (1.f - zx) * nx + zx * hox;
            float hy = (1.f - zy) * ny + zy * hoy;
            sH2[rl * 128 + 2 * d2]     = make_float2(hx, hx);
            sH2[rl * 128 + 2 * d2 + 1] = make_float2(hy, hy);
            float m = sM[rl * 10 + s];
            msum[i].x += m * hx;
            msum[i].y += m * hy;
        }
        __syncthreads();
    }
#pragma unroll
    for (int i = 0; i < 4; i++) {
        int rl = rpart * 4 + i;
        int bg = b0 + rl;
        float invc = 1.f / sCnt[rl];
        ((float2*)g_S)[((size_t)lt * BB + bg) * 64 + d2] =
            make_float2(msum[i].x * invc, msum[i].y * invc);
    }
}

// ---------------- 4) attention combine (2 layers) ----------------
__device__ __forceinline__ float blkred(float v, float* red) {
    int d = threadIdx.x;
    red[d] = v;
    __syncthreads();
#pragma unroll
    for (int st = 64; st > 0; st >>= 1) {
        if (d < st) red[d] += red[d + st];
        __syncthreads();
    }
    float r = red[0];
    __syncthreads();
    return r;
}

__global__ __launch_bounds__(128) void final_kernel(
    const float* __restrict__ att, const int* __restrict__ ids,
    float* __restrict__ out)
{
    __shared__ float red[128];
    __shared__ float sC[3][128];
    int b = blockIdx.x, d = threadIdx.x;
    float h = g_E_drug[(size_t)ids[b] * 128 + d];
#pragma unroll
    for (int l = 0; l < 2; l++) {
        for (int t = 0; t < 3; t++)
            sC[t][d] = g_S[((size_t)(l * 3 + t) * BB + b) * 128 + d];
        __syncthreads();
        float a1 = att[l * 256 + d], a2 = att[l * 256 + 128 + d];
        float dh1 = blkred(h * a1, red);
        float dh2 = blkred(h * a2, red);
        float e0 = dh1 + dh2;
        float e1 = dh1 + blkred(sC[0][d] * a2, red);
        float e2 = dh1 + blkred(sC[1][d] * a2, red);
        float e3 = dh1 + blkred(sC[2][d] * a2, red);
        e0 = e0 > 0.f ? e0 : 0.01f * e0;
        e1 = e1 > 0.f ? e1 : 0.01f * e1;
        e2 = e2 > 0.f ? e2 : 0.01f * e2;
        e3 = e3 > 0.f ? e3 : 0.01f * e3;
        float mx = fmaxf(fmaxf(e0, e1), fmaxf(e2, e3));
        float w0 = __expf(e0 - mx), w1 = __expf(e1 - mx);
        float w2 = __expf(e2 - mx), w3 = __expf(e3 - mx);
        float inv = __fdividef(1.f, w0 + w1 + w2 + w3);
        h = (w0 * h + w1 * sC[0][d] + w2 * sC[1][d] + w3 * sC[2][d]) * inv;
        __syncthreads();
    }
    out[(size_t)b * 128 + d] = h;
}

// ---------------- launch ----------------
extern "C" void kernel_launch(void* const* d_in, const int* in_sizes, int n_in,
                              void* d_out, int out_size)
{
    const float* drug = (const float*)d_in[0];
    const float* gene = (const float*)d_in[1];
    const float* cell = (const float*)d_in[2];
    const float* Wd = (const float*)d_in[3];
    const float* bd = (const float*)d_in[4];
    const float* Wg = (const float*)d_in[5];
    const float* bg = (const float*)d_in[6];
    const float* Wc = (const float*)d_in[7];
    const float* bc = (const float*)d_in[8];
    const float* gW = (const float*)d_in[9];
    const float* gU = (const float*)d_in[10];
    const float* gb = (const float*)d_in[11];
    const float* att = (const float*)d_in[12];
    const int* ids = (const int*)d_in[13];
    const int* nd = (const int*)d_in[14];
    const int* ng = (const int*)d_in[15];
    const int* nc = (const int*)d_in[16];
    float* out = (float*)d_out;

    const int XW_SMEM  = 2 * 32 * 384 * 4 + 64 * 128 * 8 + 64 * 4;        // 164_352
    const int GRU_SMEM = 128 * 384 * 4 + 32 * 128 * 8 + 320 * 4 + 32 * 4; // 230784
    cudaFuncSetAttribute(xw_kernel, cudaFuncAttributeMaxDynamicSharedMemorySize, XW_SMEM);
    cudaFuncSetAttribute(gru_kernel, cudaFuncAttributeMaxDynamicSharedMemorySize, GRU_SMEM);

    // 1) project tables once
    proj_kernel<<<(ND + 127) / 128, 256>>>(drug, Wd, bd, 0, ND, 2048);
    proj_kernel<<<(NG + 127) / 128, 256>>>(gene, Wg, bg, 1, NG, 1024);
    proj_kernel<<<(NC + 127) / 128, 256>>>(cell, Wc, bc, 2, NC, 512);

    // 2) XW = gathered X @ W + b for all 6 (layer,type)
    xw_kernel<<<dim3(40960 / 64, 6), 512, XW_SMEM>>>(gW, gb, nd, ng, nc);

    // 3) GRU recurrence + masked mean for all 6 (layer,type)
    gru_kernel<<<dim3(BB / 32, 6), 512, GRU_SMEM>>>(gU, nd, ng, nc);

    // 4) attention combine (both layers) + output
    final_kernel<<<BB, 128>>>(att, ids, out);
}

// round 7
// speedup vs baseline: 1.6449x; 1.6449x over previous
#include <cuda_runtime.h>
#include <cuda_bf16.h>

typedef unsigned long long u64;
typedef unsigned u32;

#define ND 20000
#define NG 20000
#define NC 10000
#define BB 4096

__device__ float g_E_drug[ND * 128];
__device__ float g_E_gene[NG * 128];
__device__ float g_E_cell[NC * 128];
__device__ float g_XW[6 * BB * 10 * 384];
__device__ float g_S[6 * BB * 128];
// transposed bf16-split weights [N][K]: [d | g | c | x(6 lt)]
#define WOFF_D 0
#define WOFF_G 262144
#define WOFF_C 393216
#define WOFF_X 458752
__device__ __nv_bfloat16 g_WT_hi[753664];
__device__ __nv_bfloat16 g_WT_lo[753664];

// ---------------- scalar helpers ----------------
__device__ __forceinline__ u64 fma2(u64 a, u64 b, u64 c) {
    u64 d;
    asm("fma.rn.f32x2 %0, %1, %2, %3;" : "=l"(d) : "l"(a), "l"(b), "l"(c));
    return d;
}
__device__ __forceinline__ float2 unpack2(u64 a) {
    u32 lo, hi;
    asm("mov.b64 {%0, %1}, %2;" : "=r"(lo), "=r"(hi) : "l"(a));
    return make_float2(__uint_as_float(lo), __uint_as_float(hi));
}
__device__ __forceinline__ float sigmf(float x) {
    return __fdividef(1.f, 1.f + __expf(-x));
}
__device__ __forceinline__ float tanh_fast(float x) {
    float ax = fabsf(x);
    float e = __expf(-2.f * ax);
    return copysignf(__fdividef(1.f - e, 1.f + e), x);
}
// {lo=bf16_trunc(a_fp32), hi=bf16_trunc(b_fp32)}
__device__ __forceinline__ u32 hipack(u32 a, u32 b) {
    u32 d;
    asm("prmt.b32 %0, %1, %2, 0x7632;" : "=r"(d) : "r"(a), "r"(b));
    return d;
}
// {lo=bf16_rn(a), hi=bf16_rn(b)}
#define PACKBF2(r, a, b) \
    asm("cvt.rn.satfinite.bf16x2.f32 %0, %1, %2;" : "=r"(r) : "f"(b), "f"(a))

#define MMA_BF16(c, a0, a1, a2, a3, b0, b1) \
    asm volatile("mma.sync.aligned.m16n8k16.row.col.f32.bf16.bf16.f32 " \
        "{%0,%1,%2,%3}, {%4,%5,%6,%7}, {%8,%9}, {%0,%1,%2,%3};" \
        : "+f"((c)[0]), "+f"((c)[1]), "+f"((c)[2]), "+f"((c)[3]) \
        : "r"(a0), "r"(a1), "r"(a2), "r"(a3), "r"(b0), "r"(b1))

// ---------------- 0) transpose + split W: src [lt][K][N] -> WT [lt][N][K] ----
__global__ void wsplit_kernel(const float* __restrict__ W, int dstoff, int K, int N)
{
    int lt = blockIdx.y;
    const float* src = W + (size_t)lt * K * N;
    __nv_bfloat16* hi = g_WT_hi + dstoff + (size_t)lt * K * N;
    __nv_bfloat16* lo = g_WT_lo + dstoff + (size_t)lt * K * N;
    int total = K * N;
    for (int i = blockIdx.x * blockDim.x + threadIdx.x; i < total; i += gridDim.x * blockDim.x) {
        int k = i / N, n = i - k * N;
        float w = src[i];
        u32 u = __float_as_uint(w);
        __nv_bfloat16_raw hr; hr.x = (unsigned short)(u >> 16);
        hi[(size_t)n * K + k] = __nv_bfloat16(hr);
        lo[(size_t)n * K + k] = __float2bfloat16(w - __uint_as_float(u & 0xffff0000u));
    }
}

// ---------------- 1) proj: E = F @ W + b via mma.sync bf16 hi/lo ------------
// 256 thr (8 warps). CTA tile 128 rows x 128 cols. K-tiles of 64.
// smem u32 pitch 36 (=4 mod 32 -> banks 4g+t conflict-free).
__global__ __launch_bounds__(256, 2) void proj_mma(
    const float* __restrict__ F, const float* __restrict__ bias,
    int sel, int N, int K)
{
    extern __shared__ u32 sm32[];
    u32* sAh = sm32;               // 128*36
    u32* sAl = sAh + 4608;
    u32* sBh = sAl + 4608;
    u32* sBl = sBh + 4608;

    int woff = (sel == 0) ? WOFF_D : (sel == 1) ? WOFF_G : WOFF_C;
    const __nv_bfloat16* WTh = g_WT_hi + woff;
    const __nv_bfloat16* WTl = g_WT_lo + woff;
    float* E = (sel == 0) ? g_E_drug : (sel == 1) ? g_E_gene : g_E_cell;

    int tid = threadIdx.x, wm = tid >> 5, lane = tid & 31;
    int g = lane >> 2, t = lane & 3;
    int row0 = blockIdx.x * 128;

    float acc[16][4];
#pragma unroll
    for (int j = 0; j < 16; j++)
#pragma unroll
        for (int q = 0; q < 4; q++) acc[j][q] = 0.f;

    int srow = tid >> 1, skh = (tid & 1) * 32;
    int aclamp = row0 + srow < N ? row0 + srow : N - 1;
    const float* Abase = F + (size_t)aclamp * K;

    for (int kc = 0; kc < K; kc += 64) {
        __syncthreads();
        {   // stage A 128x64 fp32 -> hi/lo bf16 pairs
            const float4* src = (const float4*)(Abase + kc + skh);
            u32* dh = sAh + srow * 36 + (skh >> 1);
            u32* dl = sAl + srow * 36 + (skh >> 1);
#pragma unroll
            for (int i = 0; i < 8; i++) {
                float4 f = src[i];
                u32 ux = __float_as_uint(f.x), uy = __float_as_uint(f.y);
                u32 uz = __float_as_uint(f.z), uw = __float_as_uint(f.w);
                dh[i * 2]     = hipack(ux, uy);
                dh[i * 2 + 1] = hipack(uz, uw);
                float lx = f.x - __uint_as_float(ux & 0xffff0000u);
                float ly = f.y - __uint_as_float(uy & 0xffff0000u);
                float lz = f.z - __uint_as_float(uz & 0xffff0000u);
                float lw = f.w - __uint_as_float(uw & 0xffff0000u);
                u32 l0, l1;
                PACKBF2(l0, lx, ly);
                PACKBF2(l1, lz, lw);
                dl[i * 2] = l0; dl[i * 2 + 1] = l1;
            }
        }
        {   // stage B 128n x 64k (bf16 copy)
            const uint4* bh = (const uint4*)(WTh + (size_t)srow * K + kc + skh);
            const uint4* bl = (const uint4*)(WTl + (size_t)srow * K + kc + skh);
            uint4* dh = (uint4*)(sBh + srow * 36 + (skh >> 1));
            uint4* dl = (uint4*)(sBl + srow * 36 + (skh >> 1));
#pragma unroll
            for (int i = 0; i < 4; i++) { dh[i] = bh[i]; dl[i] = bl[i]; }
        }
        __syncthreads();

#pragma unroll
        for (int ks = 0; ks < 4; ks++) {
            int ab = (wm * 16 + g) * 36 + ks * 8 + t;
            u32 ah0 = sAh[ab],       ah1 = sAh[ab + 288];
            u32 ah2 = sAh[ab + 4],   ah3 = sAh[ab + 292];
            u32 al0 = sAl[ab],       al1 = sAl[ab + 288];
            u32 al2 = sAl[ab + 4],   al3 = sAl[ab + 292];
#pragma unroll
            for (int j = 0; j < 16; j++) {
                int bb = (j * 8 + g) * 36 + ks * 8 + t;
                u32 bh0 = sBh[bb], bh1 = sBh[bb + 4];
                u32 bl0 = sBl[bb], bl1 = sBl[bb + 4];
                MMA_BF16(acc[j], ah0, ah1, ah2, ah3, bh0, bh1);
                MMA_BF16(acc[j], al0, al1, al2, al3, bh0, bh1);
                MMA_BF16(acc[j], ah0, ah1, ah2, ah3, bl0, bl1);
            }
        }
    }

    int r0 = row0 + wm * 16 + g;
#pragma unroll
    for (int j = 0; j < 16; j++) {
        int col = j * 8 + 2 * t;
        float bx = bias[col], by = bias[col + 1];
        if (r0 < N)
            *(float2*)(E + (size_t)r0 * 128 + col) =
                make_float2(acc[j][0] + bx, acc[j][1] + by);
        if (r0 + 8 < N)
            *(float2*)(E + (size_t)(r0 + 8) * 128 + col) =
                make_float2(acc[j][2] + bx, acc[j][3] + by);
    }
}

// ---------------- 2) xw: XW = gather(E) @ gruW + b via mma.sync -------------
// 256 thr. CTA: 128 gathered rows, K=128 staged once; 6 n-chunks of 64.
// smem u32 pitch 68 (=4 mod 32).
__global__ __launch_bounds__(256, 2) void xw_mma(
    const float* __restrict__ gruB,
    const int* __restrict__ nd, const int* __restrict__ ng,
    const int* __restrict__ pnc)
{
    extern __shared__ u32 sm32[];
    u32* sAh = sm32;               // 128*68
    u32* sAl = sAh + 8704;
    u32* sBh = sAl + 8704;         // 64*68
    u32* sBl = sBh + 4352;

    int tid = threadIdx.x, wm = tid >> 5, lane = tid & 31;
    int g = lane >> 2, t = lane & 3;
    int lt = blockIdx.y, t3 = lt % 3;
    const int* nbr = (t3 == 0) ? nd : (t3 == 1) ? ng : pnc;
    const float* Etab = (t3 == 0) ? g_E_drug : (t3 == 1) ? g_E_gene : g_E_cell;
    const __nv_bfloat16* WTh = g_WT_hi + WOFF_X + lt * 49152;
    const __nv_bfloat16* WTl = g_WT_lo + WOFF_X + lt * 49152;
    const float* bias = gruB + lt * 384;
    float* out = g_XW + (size_t)lt * 40960 * 384;
    int row0 = blockIdx.x * 128;

    {   // stage A (gathered, K=128) once
        int srow = tid >> 1, skh = (tid & 1) * 64;
        int id = nbr[row0 + srow];
        bool v = (id >= 0);
        const float4* src = (const float4*)(Etab + (size_t)(v ? id : 0) * 128 + skh);
        u32* dh = sAh + srow * 68 + (skh >> 1);
        u32* dl = sAl + srow * 68 + (skh >> 1);
#pragma unroll
        for (int i = 0; i < 16; i++) {
            float4 f = v ? src[i] : make_float4(0.f, 0.f, 0.f, 0.f);
            u32 ux = __float_as_uint(f.x), uy = __float_as_uint(f.y);
            u32 uz = __float_as_uint(f.z), uw = __float_as_uint(f.w);
            dh[i * 2]     = hipack(ux, uy);
            dh[i * 2 + 1] = hipack(uz, uw);
            float lx = f.x - __uint_as_float(ux & 0xffff0000u);
            float ly = f.y - __uint_as_float(uy & 0xffff0000u);
            float lz = f.z - __uint_as_float(uz & 0xffff0000u);
            float lw = f.w - __uint_as_float(uw & 0xffff0000u);
            u32 l0, l1;
            PACKBF2(l0, lx, ly);
            PACKBF2(l1, lz, lw);
            dl[i * 2] = l0; dl[i * 2 + 1] = l1;
        }
    }

    for (int ncb = 0; ncb < 6; ncb++) {
        __syncthreads();
        {   // stage B chunk: 64n x 128k
            int brow = tid >> 2, kq = (tid & 3) * 32;
            const uint4* bh = (const uint4*)(WTh + (size_t)(ncb * 64 + brow) * 128 + kq);
            const uint4* bl = (const uint4*)(WTl + (size_t)(ncb * 64 + brow) * 128 + kq);
            uint4* dh = (uint4*)(sBh + brow * 68 + (kq >> 1));
            uint4* dl = (uint4*)(sBl + brow * 68 + (kq >> 1));
#pragma unroll
            for (int i = 0; i < 4; i++) { dh[i] = bh[i]; dl[i] = bl[i]; }
        }
        __syncthreads();

        float acc[8][4];
#pragma unroll
        for (int j = 0; j < 8; j++)
#pragma unroll
            for (int q = 0; q < 4; q++) acc[j][q] = 0.f;

#pragma unroll
        for (int ks = 0; ks < 8; ks++) {
            int ab = (wm * 16 + g) * 68 + ks * 8 + t;
            u32 ah0 = sAh[ab],     ah1 = sAh[ab + 544];
            u32 ah2 = sAh[ab + 4], ah3 = sAh[ab + 548];
            u32 al0 = sAl[ab],     al1 = sAl[ab + 544];
            u32 al2 = sAl[ab + 4], al3 = sAl[ab + 548];
#pragma unroll
            for (int j = 0; j < 8; j++) {
                int bb = (j * 8 + g) * 68 + ks * 8 + t;
                u32 bh0 = sBh[bb], bh1 = sBh[bb + 4];
                u32 bl0 = sBl[bb], bl1 = sBl[bb + 4];
                MMA_BF16(acc[j], ah0, ah1, ah2, ah3, bh0, bh1);
                MMA_BF16(acc[j], al0, al1, al2, al3, bh0, bh1);
                MMA_BF16(acc[j], ah0, ah1, ah2, ah3, bl0, bl1);
            }
        }

        int r0 = row0 + wm * 16 + g;
#pragma unroll
        for (int j = 0; j < 8; j++) {
            int col = ncb * 64 + j * 8 + 2 * t;
            float bx = bias[col], by = bias[col + 1];
            *(float2*)(out + (size_t)r0 * 384 + col) =
                make_float2(acc[j][0] + bx, acc[j][1] + by);
            *(float2*)(out + (size_t)(r0 + 8) * 384 + col) =
                make_float2(acc[j][2] + bx, acc[j][3] + by);
        }
    }
}

// ---------------- 3) GRU recurrence + masked mean (R4 passing version) -------
__global__ __launch_bounds__(512) void gru_kernel(
    const float* __restrict__ gruU,
    const int* __restrict__ nbr_d, const int* __restrict__ nbr_g,
    const int* __restrict__ nbr_c)
{
    extern __shared__ float sm[];
    float*  sU  = sm;
    float2* sH2 = (float2*)(sm + 49152);
    float*  sM  = (float*)(sH2 + 32 * 128);
    float*  sCnt = sM + 320;

    int tid = threadIdx.x;
    int lt = blockIdx.y;
    int t3 = lt % 3;
    const int* nbr = (t3 == 0) ? nbr_d : (t3 == 1) ? nbr_g : nbr_c;
    int b0 = blockIdx.x * 32;

    {
        const float4* src = (const float4*)(gruU + (size_t)lt * 49152);
        float4* dst = (float4*)sU;
#pragma unroll
        for (int i = 0; i < 24; i++) dst[tid + i * 512] = src[tid + i * 512];
    }
    if (tid < 320) {
        int rr = tid / 10, s = tid % 10;
        sM[tid] = (nbr[(size_t)(b0 + rr) * 10 + s] >= 0) ? 1.f : 0.f;
    }
    for (int i = tid; i < 4096; i += 512) sH2[i] = make_float2(0.f, 0.f);
    __syncthreads();
    if (tid < 32) {
        float cnt = 0.f;
        for (int s = 0; s < 10; s++) cnt += sM[tid * 10 + s];
        sCnt[tid] = fmaxf(cnt, 1.f);
    }
    __syncthreads();

    int d2 = tid & 63, rpart = tid >> 6;
    float2 msum[4];
#pragma unroll
    for (int i = 0; i < 4; i++) msum[i] = make_float2(0.f, 0.f);

    for (int s = 0; s < 10; s++) {
        float2 pxz[4], pxr[4], pxn[4];
#pragma unroll
        for (int i = 0; i < 4; i++) {
            int bg = b0 + rpart * 4 + i;
            const float* xwb = g_XW + ((size_t)lt * 40960 + (size_t)bg * 10 + s) * 384;
            pxz[i] = *(const float2*)(xwb + 2 * d2);
            pxr[i] = *(const float2*)(xwb + 128 + 2 * d2);
            pxn[i] = *(const float2*)(xwb + 256 + 2 * d2);
        }
        u64 az[4], ar[4], an[4];
#pragma unroll
        for (int i = 0; i < 4; i++) { az[i] = 0ull; ar[i] = 0ull; an[i] = 0ull; }
#pragma unroll 4
        for (int k = 0; k < 128; k++) {
            u64 uz = *(const u64*)(sU + k * 384 + 2 * d2);
            u64 ur = *(const u64*)(sU + k * 384 + 128 + 2 * d2);
            u64 un = *(const u64*)(sU + k * 384 + 256 + 2 * d2);
#pragma unroll
            for (int i = 0; i < 4; i++) {
                u64 hh = *(const u64*)(sH2 + (rpart * 4 + i) * 128 + k);
                az[i] = fma2(hh, uz, az[i]);
                ar[i] = fma2(hh, ur, ar[i]);
                an[i] = fma2(hh, un, an[i]);
            }
        }
        __syncthreads();
#pragma unroll
        for (int i = 0; i < 4; i++) {
            int rl = rpart * 4 + i;
            float2 hz = unpack2(az[i]), hr = unpack2(ar[i]), hn = unpack2(an[i]);
            float hox = sH2[rl * 128 + 2 * d2].x;
            float hoy = sH2[rl * 128 + 2 * d2 + 1].x;
            float zx = sigmf(pxz[i].x + hz.x), zy = sigmf(pxz[i].y + hz.y);
            float rx = sigmf(pxr[i].x + hr.x), ry = sigmf(pxr[i].y + hr.y);
            float nx = tanh_fast(pxn[i].x + rx * hn.x);
            float ny = tanh_fast(pxn[i].y + ry * hn.y);
            float hx = (1.f - zx) * nx + zx * hox;
            float hy = (1.f - zy) * ny + zy * hoy;
            sH2[rl * 128 + 2 * d2]     = make_float2(hx, hx);
            sH2[rl * 128 + 2 * d2 + 1] = make_float2(hy, hy);
            float m = sM[rl * 10 + s];
            msum[i].x += m * hx;
            msum[i].y += m * hy;
        }
        __syncthreads();
    }
#pragma unroll
    for (int i = 0; i < 4; i++) {
        int rl = rpart * 4 + i;
        int bg = b0 + rl;
        float invc = 1.f / sCnt[rl];
        ((float2*)g_S)[((size_t)lt * BB + bg) * 64 + d2] =
            make_float2(msum[i].x * invc, msum[i].y * invc);
    }
}

// ---------------- 4) attention combine ----------------
__device__ __forceinline__ float blkred(float v, float* red) {
    int d = threadIdx.x;
    red[d] = v;
    __syncthreads();
#pragma unroll
    for (int st = 64; st > 0; st >>= 1) {
        if (d < st) red[d] += red[d + st];
        __syncthreads();
    }
    float r = red[0];
    __syncthreads();
    return r;
}

__global__ __launch_bounds__(128) void final_kernel(
    const float* __restrict__ att, const int* __restrict__ ids,
    float* __restrict__ out)
{
    __shared__ float red[128];
    __shared__ float sC[3][128];
    int b = blockIdx.x, d = threadIdx.x;
    float h = g_E_drug[(size_t)ids[b] * 128 + d];
#pragma unroll
    for (int l = 0; l < 2; l++) {
        for (int t = 0; t < 3; t++)
            sC[t][d] = g_S[((size_t)(l * 3 + t) * BB + b) * 128 + d];
        __syncthreads();
        float a1 = att[l * 256 + d], a2 = att[l * 256 + 128 + d];
        float dh1 = blkred(h * a1, red);
        float dh2 = blkred(h * a2, red);
        float e0 = dh1 + dh2;
        float e1 = dh1 + blkred(sC[0][d] * a2, red);
        float e2 = dh1 + blkred(sC[1][d] * a2, red);
        float e3 = dh1 + blkred(sC[2][d] * a2, red);
        e0 = e0 > 0.f ? e0 : 0.01f * e0;
        e1 = e1 > 0.f ? e1 : 0.01f * e1;
        e2 = e2 > 0.f ? e2 : 0.01f * e2;
        e3 = e3 > 0.f ? e3 : 0.01f * e3;
        float mx = fmaxf(fmaxf(e0, e1), fmaxf(e2, e3));
        float w0 = __expf(e0 - mx), w1 = __expf(e1 - mx);
        float w2 = __expf(e2 - mx), w3 = __expf(e3 - mx);
        float inv = __fdividef(1.f, w0 + w1 + w2 + w3);
        h = (w0 * h + w1 * sC[0][d] + w2 * sC[1][d] + w3 * sC[2][d]) * inv;
        __syncthreads();
    }
    out[(size_t)b * 128 + d] = h;
}

// ---------------- launch ----------------
extern "C" void kernel_launch(void* const* d_in, const int* in_sizes, int n_in,
                              void* d_out, int out_size)
{
    const float* drug = (const float*)d_in[0];
    const float* gene = (const float*)d_in[1];
    const float* cell = (const float*)d_in[2];
    const float* Wd = (const float*)d_in[3];
    const float* bd = (const float*)d_in[4];
    const float* Wg = (const float*)d_in[5];
    const float* bg = (const float*)d_in[6];
    const float* Wc = (const float*)d_in[7];
    const float* bc = (const float*)d_in[8];
    const float* gW = (const float*)d_in[9];
    const float* gU = (const float*)d_in[10];
    const float* gb = (const float*)d_in[11];
    const float* att = (const float*)d_in[12];
    const int* ids = (const int*)d_in[13];
    const int* nd = (const int*)d_in[14];
    const int* ng = (const int*)d_in[15];
    const int* nc = (const int*)d_in[16];
    float* out = (float*)d_out;

    const int PROJ_SMEM = 4 * 4608 * 4;                 // 73728
    const int XW_SMEM   = (2 * 8704 + 2 * 4352) * 4;    // 104448
    const int GRU_SMEM  = 128 * 384 * 4 + 32 * 128 * 8 + 320 * 4 + 32 * 4;
    cudaFuncSetAttribute(proj_mma, cudaFuncAttributeMaxDynamicSharedMemorySize, PROJ_SMEM);
    cudaFuncSetAttribute(xw_mma, cudaFuncAttributeMaxDynamicSharedMemorySize, XW_SMEM);
    cudaFuncSetAttribute(gru_kernel, cudaFuncAttributeMaxDynamicSharedMemorySize, GRU_SMEM);

    // 0) weight transpose + bf16 split
    wsplit_kernel<<<dim3(64, 1), 256>>>(Wd, WOFF_D, 2048, 128);
    wsplit_kernel<<<dim3(32, 1), 256>>>(Wg, WOFF_G, 1024, 128);
    wsplit_kernel<<<dim3(16, 1), 256>>>(Wc, WOFF_C, 512, 128);
    wsplit_kernel<<<dim3(16, 6), 256>>>(gW, WOFF_X, 128, 384);

    // 1) project tables (tensor cores, hi/lo split)
    proj_mma<<<157, 256, PROJ_SMEM>>>(drug, bd, 0, ND, 2048);
    proj_mma<<<157, 256, PROJ_SMEM>>>(gene, bg, 1, NG, 1024);
    proj_mma<<<79, 256, PROJ_SMEM>>>(cell, bc, 2, NC, 512);

    // 2) XW = gathered E @ gru_W + gru_b for all 6 (layer,type)
    xw_mma<<<dim3(320, 6), 256, XW_SMEM>>>(gb, nd, ng, nc);

    // 3) GRU recurrence + masked mean
    gru_kernel<<<dim3(BB / 32, 6), 512, GRU_SMEM>>>(gU, nd, ng, nc);

    // 4) attention combine + output
    final_kernel<<<BB, 128>>>(att, ids, out);
}

// round 9
// speedup vs baseline: 2.3356x; 1.4200x over previous
#include <cuda_runtime.h>
#include <cuda_bf16.h>

typedef unsigned long long u64;
typedef unsigned u32;

#define ND 20000
#define NG 20000
#define NC 10000
#define BB 4096

__device__ float g_E_drug[ND * 128];
__device__ float g_E_gene[NG * 128];
__device__ float g_E_cell[NC * 128];
__device__ float g_XW[6 * BB * 10 * 384];
__device__ float g_S[6 * BB * 128];
// transposed bf16-split weights [N][K]: [d | g | c | x(6) | u(6)]
#define WOFF_D 0
#define WOFF_G 262144
#define WOFF_C 393216
#define WOFF_X 458752
#define WOFF_U 753664
__device__ __nv_bfloat16 g_WT_hi[1048576];
__device__ __nv_bfloat16 g_WT_lo[1048576];

// ---------------- scalar helpers ----------------
__device__ __forceinline__ float sigmf(float x) {
    return __fdividef(1.f, 1.f + __expf(-x));
}
__device__ __forceinline__ float tanh_fast(float x) {
    float ax = fabsf(x);
    float e = __expf(-2.f * ax);
    return copysignf(__fdividef(1.f - e, 1.f + e), x);
}
// {lo=bf16_trunc(a_fp32bits), hi=bf16_trunc(b_fp32bits)}
__device__ __forceinline__ u32 hipack(u32 a, u32 b) {
    u32 d;
    asm("prmt.b32 %0, %1, %2, 0x7632;" : "=r"(d) : "r"(a), "r"(b));
    return d;
}
#define PACKBF2(r, a, b) \
    asm("cvt.rn.satfinite.bf16x2.f32 %0, %1, %2;" : "=r"(r) : "f"(b), "f"(a))

#define MMA_BF16(c, a0, a1, a2, a3, b0, b1) \
    asm volatile("mma.sync.aligned.m16n8k16.row.col.f32.bf16.bf16.f32 " \
        "{%0,%1,%2,%3}, {%4,%5,%6,%7}, {%8,%9}, {%0,%1,%2,%3};" \
        : "+f"((c)[0]), "+f"((c)[1]), "+f"((c)[2]), "+f"((c)[3]) \
        : "r"(a0), "r"(a1), "r"(a2), "r"(a3), "r"(b0), "r"(b1))

// ---------------- 0) transpose + split W: src [lt][K][N] -> WT [lt][N][K] ----
__global__ void wsplit_kernel(const float* __restrict__ W, int dstoff, int K, int N)
{
    int lt = blockIdx.y;
    const float* src = W + (size_t)lt * K * N;
    __nv_bfloat16* hi = g_WT_hi + dstoff + (size_t)lt * K * N;
    __nv_bfloat16* lo = g_WT_lo + dstoff + (size_t)lt * K * N;
    int total = K * N;
    for (int i = blockIdx.x * blockDim.x + threadIdx.x; i < total; i += gridDim.x * blockDim.x) {
        int k = i / N, n = i - k * N;
        float w = src[i];
        u32 u = __float_as_uint(w);
        __nv_bfloat16_raw hr; hr.x = (unsigned short)(u >> 16);
        hi[(size_t)n * K + k] = __nv_bfloat16(hr);
        lo[(size_t)n * K + k] = __float2bfloat16(w - __uint_as_float(u & 0xffff0000u));
    }
}

// ---------------- 1) proj: E = F @ W + b (unchanged, passing) ---------------
__global__ __launch_bounds__(256, 2) void proj_mma(
    const float* __restrict__ F, const float* __restrict__ bias,
    int sel, int N, int K)
{
    extern __shared__ u32 sm32[];
    u32* sAh = sm32;               // 128*36
    u32* sAl = sAh + 4608;
    u32* sBh = sAl + 4608;
    u32* sBl = sBh + 4608;

    int woff = (sel == 0) ? WOFF_D : (sel == 1) ? WOFF_G : WOFF_C;
    const __nv_bfloat16* WTh = g_WT_hi + woff;
    const __nv_bfloat16* WTl = g_WT_lo + woff;
    float* E = (sel == 0) ? g_E_drug : (sel == 1) ? g_E_gene : g_E_cell;

    int tid = threadIdx.x, wm = tid >> 5, lane = tid & 31;
    int g = lane >> 2, t = lane & 3;
    int row0 = blockIdx.x * 128;

    float acc[16][4];
#pragma unroll
    for (int j = 0; j < 16; j++)
#pragma unroll
        for (int q = 0; q < 4; q++) acc[j][q] = 0.f;

    int srow = tid >> 1, skh = (tid & 1) * 32;
    int aclamp = row0 + srow < N ? row0 + srow : N - 1;
    const float* Abase = F + (size_t)aclamp * K;

    for (int kc = 0; kc < K; kc += 64) {
        __syncthreads();
        {
            const float4* src = (const float4*)(Abase + kc + skh);
            u32* dh = sAh + srow * 36 + (skh >> 1);
            u32* dl = sAl + srow * 36 + (skh >> 1);
#pragma unroll
            for (int i = 0; i < 8; i++) {
                float4 f = src[i];
                u32 ux = __float_as_uint(f.x), uy = __float_as_uint(f.y);
                u32 uz = __float_as_uint(f.z), uw = __float_as_uint(f.w);
                dh[i * 2]     = hipack(ux, uy);
                dh[i * 2 + 1] = hipack(uz, uw);
                float lx = f.x - __uint_as_float(ux & 0xffff0000u);
                float ly = f.y - __uint_as_float(uy & 0xffff0000u);
                float lz = f.z - __uint_as_float(uz & 0xffff0000u);
                float lw = f.w - __uint_as_float(uw & 0xffff0000u);
                u32 l0, l1;
                PACKBF2(l0, lx, ly);
                PACKBF2(l1, lz, lw);
                dl[i * 2] = l0; dl[i * 2 + 1] = l1;
            }
        }
        {
            const uint4* bh = (const uint4*)(WTh + (size_t)srow * K + kc + skh);
            const uint4* bl = (const uint4*)(WTl + (size_t)srow * K + kc + skh);
            uint4* dh = (uint4*)(sBh + srow * 36 + (skh >> 1));
            uint4* dl = (uint4*)(sBl + srow * 36 + (skh >> 1));
#pragma unroll
            for (int i = 0; i < 4; i++) { dh[i] = bh[i]; dl[i] = bl[i]; }
        }
        __syncthreads();

#pragma unroll
        for (int ks = 0; ks < 4; ks++) {
            int ab = (wm * 16 + g) * 36 + ks * 8 + t;
            u32 ah0 = sAh[ab],       ah1 = sAh[ab + 288];
            u32 ah2 = sAh[ab + 4],   ah3 = sAh[ab + 292];
            u32 al0 = sAl[ab],       al1 = sAl[ab + 288];
            u32 al2 = sAl[ab + 4],   al3 = sAl[ab + 292];
#pragma unroll
            for (int j = 0; j < 16; j++) {
                int bb = (j * 8 + g) * 36 + ks * 8 + t;
                u32 bh0 = sBh[bb], bh1 = sBh[bb + 4];
                u32 bl0 = sBl[bb], bl1 = sBl[bb + 4];
                MMA_BF16(acc[j], ah0, ah1, ah2, ah3, bh0, bh1);
                MMA_BF16(acc[j], al0, al1, al2, al3, bh0, bh1);
                MMA_BF16(acc[j], ah0, ah1, ah2, ah3, bl0, bl1);
            }
        }
    }

    int r0 = row0 + wm * 16 + g;
#pragma unroll
    for (int j = 0; j < 16; j++) {
        int col = j * 8 + 2 * t;
        float bx = bias[col], by = bias[col + 1];
        if (r0 < N)
            *(float2*)(E + (size_t)r0 * 128 + col) =
                make_float2(acc[j][0] + bx, acc[j][1] + by);
        if (r0 + 8 < N)
            *(float2*)(E + (size_t)(r0 + 8) * 128 + col) =
                make_float2(acc[j][2] + bx, acc[j][3] + by);
    }
}

// ---------------- 2) xw (unchanged, passing) ---------------------------------
__global__ __launch_bounds__(256, 2) void xw_mma(
    const float* __restrict__ gruB,
    const int* __restrict__ nd, const int* __restrict__ ng,
    const int* __restrict__ pnc)
{
    extern __shared__ u32 sm32[];
    u32* sAh = sm32;               // 128*68
    u32* sAl = sAh + 8704;
    u32* sBh = sAl + 8704;         // 64*68
    u32* sBl = sBh + 4352;

    int tid = threadIdx.x, wm = tid >> 5, lane = tid & 31;
    int g = lane >> 2, t = lane & 3;
    int lt = blockIdx.y, t3 = lt % 3;
    const int* nbr = (t3 == 0) ? nd : (t3 == 1) ? ng : pnc;
    const float* Etab = (t3 == 0) ? g_E_drug : (t3 == 1) ? g_E_gene : g_E_cell;
    const __nv_bfloat16* WTh = g_WT_hi + WOFF_X + lt * 49152;
    const __nv_bfloat16* WTl = g_WT_lo + WOFF_X + lt * 49152;
    const float* bias = gruB + lt * 384;
    float* out = g_XW + (size_t)lt * 40960 * 384;
    int row0 = blockIdx.x * 128;

    {
        int srow = tid >> 1, skh = (tid & 1) * 64;
        int id = nbr[row0 + srow];
        bool v = (id >= 0);
        const float4* src = (const float4*)(Etab + (size_t)(v ? id : 0) * 128 + skh);
        u32* dh = sAh + srow * 68 + (skh >> 1);
        u32* dl = sAl + srow * 68 + (skh >> 1);
#pragma unroll
        for (int i = 0; i < 16; i++) {
            float4 f = v ? src[i] : make_float4(0.f, 0.f, 0.f, 0.f);
            u32 ux = __float_as_uint(f.x), uy = __float_as_uint(f.y);
            u32 uz = __float_as_uint(f.z), uw = __float_as_uint(f.w);
            dh[i * 2]     = hipack(ux, uy);
            dh[i * 2 + 1] = hipack(uz, uw);
            float lx = f.x - __uint_as_float(ux & 0xffff0000u);
            float ly = f.y - __uint_as_float(uy & 0xffff0000u);
            float lz = f.z - __uint_as_float(uz & 0xffff0000u);
            float lw = f.w - __uint_as_float(uw & 0xffff0000u);
            u32 l0, l1;
            PACKBF2(l0, lx, ly);
            PACKBF2(l1, lz, lw);
            dl[i * 2] = l0; dl[i * 2 + 1] = l1;
        }
    }

    for (int ncb = 0; ncb < 6; ncb++) {
        __syncthreads();
        {
            int brow = tid >> 2, kq = (tid & 3) * 32;
            const uint4* bh = (const uint4*)(WTh + (size_t)(ncb * 64 + brow) * 128 + kq);
            const uint4* bl = (const uint4*)(WTl + (size_t)(ncb * 64 + brow) * 128 + kq);
            uint4* dh = (uint4*)(sBh + brow * 68 + (kq >> 1));
            uint4* dl = (uint4*)(sBl + brow * 68 + (kq >> 1));
#pragma unroll
            for (int i = 0; i < 4; i++) { dh[i] = bh[i]; dl[i] = bl[i]; }
        }
        __syncthreads();

        float acc[8][4];
#pragma unroll
        for (int j = 0; j < 8; j++)
#pragma unroll
            for (int q = 0; q < 4; q++) acc[j][q] = 0.f;

#pragma unroll
        for (int ks = 0; ks < 8; ks++) {
            int ab = (wm * 16 + g) * 68 + ks * 8 + t;
            u32 ah0 = sAh[ab],     ah1 = sAh[ab + 544];
            u32 ah2 = sAh[ab + 4], ah3 = sAh[ab + 548];
            u32 al0 = sAl[ab],     al1 = sAl[ab + 544];
            u32 al2 = sAl[ab + 4], al3 = sAl[ab + 548];
#pragma unroll
            for (int j = 0; j < 8; j++) {
                int bb = (j * 8 + g) * 68 + ks * 8 + t;
                u32 bh0 = sBh[bb], bh1 = sBh[bb + 4];
                u32 bl0 = sBl[bb], bl1 = sBl[bb + 4];
                MMA_BF16(acc[j], ah0, ah1, ah2, ah3, bh0, bh1);
                MMA_BF16(acc[j], al0, al1, al2, al3, bh0, bh1);
                MMA_BF16(acc[j], ah0, ah1, ah2, ah3, bl0, bl1);
            }
        }

        int r0 = row0 + wm * 16 + g;
#pragma unroll
        for (int j = 0; j < 8; j++) {
            int col = ncb * 64 + j * 8 + 2 * t;
            float bx = bias[col], by = bias[col + 1];
            *(float2*)(out + (size_t)r0 * 384 + col) =
                make_float2(acc[j][0] + bx, acc[j][1] + by);
            *(float2*)(out + (size_t)(r0 + 8) * 384 + col) =
                make_float2(acc[j][2] + bx, acc[j][3] + by);
        }
    }
}

// ---------------- 3) GRU recurrence via mma.sync (mask staging FIXED) --------
__global__ __launch_bounds__(256, 1) void gru_mma(
    const int* __restrict__ nd, const int* __restrict__ ng,
    const int* __restrict__ pnc)
{
    extern __shared__ u32 sg[];
    u32* sBh = sg;                  // 384*64
    u32* sBl = sBh + 24576;
    u32* sAh = sBl + 24576;         // 32*68 (H hi)
    u32* sAl = sAh + 2176;
    float* sM = (float*)(sAl + 2176);   // 320
    float* sCnt = sM + 320;             // 32

    int tid = threadIdx.x, wm = tid >> 5, lane = tid & 31;
    int g = lane >> 2, t = lane & 3;
    int lt = blockIdx.y, t3 = lt % 3;
    const int* nbr = (t3 == 0) ? nd : (t3 == 1) ? ng : pnc;
    int b0 = blockIdx.x * 32;
    const u32* UTh = (const u32*)(g_WT_hi + WOFF_U + lt * 49152);
    const u32* UTl = (const u32*)(g_WT_lo + WOFF_U + lt * 49152);

    // stage U^T hi/lo with XOR swizzle (row n, u32 x -> x ^ ((n&7)<<2))
    for (int i = tid; i < 6144; i += 256) {
        int n = i >> 4;
        int xi = (i & 15) << 2;
        u32 dst = n * 64 + (xi ^ ((n & 7) << 2));
        *(uint4*)(sBh + dst) = *(const uint4*)(UTh + n * 64 + xi);
        *(uint4*)(sBl + dst) = *(const uint4*)(UTl + n * 64 + xi);
    }
    // FIX (R8): strided loop — blockDim is 256, sM has 320 entries
    for (int i = tid; i < 320; i += 256) {
        int rr = i / 10, s = i % 10;
        sM[i] = (nbr[(size_t)(b0 + rr) * 10 + s] >= 0) ? 1.f : 0.f;
    }
    for (int i = tid; i < 2176; i += 256) { sAh[i] = 0u; sAl[i] = 0u; }
    __syncthreads();
    if (tid < 32) {
        float c = 0.f;
        for (int s = 0; s < 10; s++) c += sM[tid * 10 + s];
        sCnt[tid] = fmaxf(c, 1.f);
    }
    __syncthreads();

    float hreg[2][2][4], msum[2][2][4];
#pragma unroll
    for (int mi = 0; mi < 2; mi++)
#pragma unroll
        for (int jj = 0; jj < 2; jj++)
#pragma unroll
            for (int q = 0; q < 4; q++) { hreg[mi][jj][q] = 0.f; msum[mi][jj][q] = 0.f; }

    for (int s = 0; s < 10; s++) {
        float2 xz[2][2][2], xr[2][2][2], xn[2][2][2];
#pragma unroll
        for (int mi = 0; mi < 2; mi++)
#pragma unroll
            for (int rh = 0; rh < 2; rh++) {
                int lrow = mi * 16 + g + rh * 8;
                const float* xwb = g_XW +
                    ((size_t)lt * 40960 + (size_t)(b0 + lrow) * 10 + s) * 384;
#pragma unroll
                for (int jj = 0; jj < 2; jj++) {
                    int d0 = 16 * wm + jj * 8 + 2 * t;
                    xz[mi][jj][rh] = *(const float2*)(xwb + d0);
                    xr[mi][jj][rh] = *(const float2*)(xwb + 128 + d0);
                    xn[mi][jj][rh] = *(const float2*)(xwb + 256 + d0);
                }
            }

        float acc[2][6][4];
#pragma unroll
        for (int mi = 0; mi < 2; mi++)
#pragma unroll
            for (int j = 0; j < 6; j++)
#pragma unroll
                for (int q = 0; q < 4; q++) acc[mi][j][q] = 0.f;

#pragma unroll
        for (int ks = 0; ks < 8; ks++) {
            u32 ah[2][4], al[2][4];
#pragma unroll
            for (int mi = 0; mi < 2; mi++) {
                int ab = (mi * 16 + g) * 68 + ks * 8 + t;
                ah[mi][0] = sAh[ab];     ah[mi][1] = sAh[ab + 544];
                ah[mi][2] = sAh[ab + 4]; ah[mi][3] = sAh[ab + 548];
                al[mi][0] = sAl[ab];     al[mi][1] = sAl[ab + 544];
                al[mi][2] = sAl[ab + 4]; al[mi][3] = sAl[ab + 548];
            }
#pragma unroll
            for (int j = 0; j < 6; j++) {
                int n8 = (j >> 1) * 16 + 2 * wm + (j & 1);
                int nrow = n8 * 8 + g;
                u32 sw = (u32)((nrow & 7) << 2);
                u32 base = (u32)nrow * 64;
                u32 x0 = ((u32)(ks * 8 + t)) ^ sw;
                u32 x1 = ((u32)(ks * 8 + t + 4)) ^ sw;
                u32 bh0 = sBh[base + x0], bh1 = sBh[base + x1];
                u32 bl0 = sBl[base + x0], bl1 = sBl[base + x1];
#pragma unroll
                for (int mi = 0; mi < 2; mi++) {
                    MMA_BF16(acc[mi][j], ah[mi][0], ah[mi][1], ah[mi][2], ah[mi][3], bh0, bh1);
                    MMA_BF16(acc[mi][j], al[mi][0], al[mi][1], al[mi][2], al[mi][3], bh0, bh1);
                    MMA_BF16(acc[mi][j], ah[mi][0], ah[mi][1], ah[mi][2], ah[mi][3], bl0, bl1);
                }
            }
        }
        __syncthreads();   // all A (H) reads done before H update

#pragma unroll
        for (int mi = 0; mi < 2; mi++)
#pragma unroll
            for (int jj = 0; jj < 2; jj++)
#pragma unroll
                for (int rh = 0; rh < 2; rh++) {
                    int q0 = rh * 2;
                    int lrow = mi * 16 + g + rh * 8;
                    float2 vz = xz[mi][jj][rh], vr = xr[mi][jj][rh], vn = xn[mi][jj][rh];
                    float z0 = sigmf(vz.x + acc[mi][jj][q0]);
                    float z1 = sigmf(vz.y + acc[mi][jj][q0 + 1]);
                    float r0 = sigmf(vr.x + acc[mi][2 + jj][q0]);
                    float r1 = sigmf(vr.y + acc[mi][2 + jj][q0 + 1]);
                    float n0 = tanh_fast(vn.x + r0 * acc[mi][4 + jj][q0]);
                    float n1 = tanh_fast(vn.y + r1 * acc[mi][4 + jj][q0 + 1]);
                    float h0 = (1.f - z0) * n0 + z0 * hreg[mi][jj][q0];
                    float h1 = (1.f - z1) * n1 + z1 * hreg[mi][jj][q0 + 1];
                    hreg[mi][jj][q0] = h0;
                    hreg[mi][jj][q0 + 1] = h1;
                    float mk = sM[lrow * 10 + s];
                    msum[mi][jj][q0]     += mk * h0;
                    msum[mi][jj][q0 + 1] += mk * h1;
                    u32 u0 = __float_as_uint(h0), u1 = __float_as_uint(h1);
                    u32 hi = hipack(u0, u1);
                    float l0f = h0 - __uint_as_float(u0 & 0xffff0000u);
                    float l1f = h1 - __uint_as_float(u1 & 0xffff0000u);
                    u32 lo;
                    PACKBF2(lo, l0f, l1f);
                    int hidx = lrow * 68 + wm * 8 + jj * 4 + t;
                    sAh[hidx] = hi;
                    sAl[hidx] = lo;
                }
        __syncthreads();   // H fully updated before next step's A loads
    }

#pragma unroll
    for (int mi = 0; mi < 2; mi++)
#pragma unroll
        for (int jj = 0; jj < 2; jj++)
#pragma unroll
            for (int rh = 0; rh < 2; rh++) {
                int q0 = rh * 2;
                int lrow = mi * 16 + g + rh * 8;
                int d0 = 16 * wm + jj * 8 + 2 * t;
                float invc = 1.f / sCnt[lrow];
                *(float2*)(g_S + ((size_t)lt * BB + b0 + lrow) * 128 + d0) =
                    make_float2(msum[mi][jj][q0] * invc, msum[mi][jj][q0 + 1] * invc);
            }
}

// ---------------- 4) attention combine ----------------
__device__ __forceinline__ float blkred(float v, float* red) {
    int d = threadIdx.x;
    red[d] = v;
    __syncthreads();
#pragma unroll
    for (int st = 64; st > 0; st >>= 1) {
        if (d < st) red[d] += red[d + st];
        __syncthreads();
    }
    float r = red[0];
    __syncthreads();
    return r;
}

__global__ __launch_bounds__(128) void final_kernel(
    const float* __restrict__ att, const int* __restrict__ ids,
    float* __restrict__ out)
{
    __shared__ float red[128];
    __shared__ float sC[3][128];
    int b = blockIdx.x, d = threadIdx.x;
    float h = g_E_drug[(size_t)ids[b] * 128 + d];
#pragma unroll
    for (int l = 0; l < 2; l++) {
        for (int t = 0; t < 3; t++)
            sC[t][d] = g_S[((size_t)(l * 3 + t) * BB + b) * 128 + d];
        __syncthreads();
        float a1 = att[l * 256 + d], a2 = att[l * 256 + 128 + d];
        float dh1 = blkred(h * a1, red);
        float dh2 = blkred(h * a2, red);
        float e0 = dh1 + dh2;
        float e1 = dh1 + blkred(sC[0][d] * a2, red);
        float e2 = dh1 + blkred(sC[1][d] * a2, red);
        float e3 = dh1 + blkred(sC[2][d] * a2, red);
        e0 = e0 > 0.f ? e0 : 0.01f * e0;
        e1 = e1 > 0.f ? e1 : 0.01f * e1;
        e2 = e2 > 0.f ? e2 : 0.01f * e2;
        e3 = e3 > 0.f ? e3 : 0.01f * e3;
        float mx = fmaxf(fmaxf(e0, e1), fmaxf(e2, e3));
        float w0 = __expf(e0 - mx), w1 = __expf(e1 - mx);
        float w2 = __expf(e2 - mx), w3 = __expf(e3 - mx);
        float inv = __fdividef(1.f, w0 + w1 + w2 + w3);
        h = (w0 * h + w1 * sC[0][d] + w2 * sC[1][d] + w3 * sC[2][d]) * inv;
        __syncthreads();
    }
    out[(size_t)b * 128 + d] = h;
}

// ---------------- launch ----------------
extern "C" void kernel_launch(void* const* d_in, const int* in_sizes, int n_in,
                              void* d_out, int out_size)
{
    const float* drug = (const float*)d_in[0];
    const float* gene = (const float*)d_in[1];
    const float* cell = (const float*)d_in[2];
    const float* Wd = (const float*)d_in[3];
    const float* bd = (const float*)d_in[4];
    const float* Wg = (const float*)d_in[5];
    const float* bg = (const float*)d_in[6];
    const float* Wc = (const float*)d_in[7];
    const float* bc = (const float*)d_in[8];
    const float* gW = (const float*)d_in[9];
    const float* gU = (const float*)d_in[10];
    const float* gb = (const float*)d_in[11];
    const float* att = (const float*)d_in[12];
    const int* ids = (const int*)d_in[13];
    const int* nd = (const int*)d_in[14];
    const int* ng = (const int*)d_in[15];
    const int* nc = (const int*)d_in[16];
    float* out = (float*)d_out;

    const int PROJ_SMEM = 4 * 4608 * 4;                 // 73728
    const int XW_SMEM   = (2 * 8704 + 2 * 4352) * 4;    // 104448
    const int GRUM_SMEM = (2 * 24576 + 2 * 2176 + 352) * 4; // 215424
    cudaFuncSetAttribute(proj_mma, cudaFuncAttributeMaxDynamicSharedMemorySize, PROJ_SMEM);
    cudaFuncSetAttribute(xw_mma, cudaFuncAttributeMaxDynamicSharedMemorySize, XW_SMEM);
    cudaFuncSetAttribute(gru_mma, cudaFuncAttributeMaxDynamicSharedMemorySize, GRUM_SMEM);

    // 0) weight transpose + bf16 split (W's and U's)
    wsplit_kernel<<<dim3(64, 1), 256>>>(Wd, WOFF_D, 2048, 128);
    wsplit_kernel<<<dim3(32, 1), 256>>>(Wg, WOFF_G, 1024, 128);
    wsplit_kernel<<<dim3(16, 1), 256>>>(Wc, WOFF_C, 512, 128);
    wsplit_kernel<<<dim3(16, 6), 256>>>(gW, WOFF_X, 128, 384);
    wsplit_kernel<<<dim3(16, 6), 256>>>(gU, WOFF_U, 128, 384);

    // 1) project tables (tensor cores, hi/lo split)
    proj_mma<<<157, 256, PROJ_SMEM>>>(drug, bd, 0, ND, 2048);
    proj_mma<<<157, 256, PROJ_SMEM>>>(gene, bg, 1, NG, 1024);
    proj_mma<<<79, 256, PROJ_SMEM>>>(cell, bc, 2, NC, 512);

    // 2) XW = gathered E @ gru_W + gru_b
    xw_mma<<<dim3(320, 6), 256, XW_SMEM>>>(gb, nd, ng, nc);

    // 3) GRU recurrence + masked mean (tensor cores)
    gru_mma<<<dim3(BB / 32, 6), 256, GRUM_SMEM>>>(nd, ng, nc);

    // 4) attention combine + output
    final_kernel<<<BB, 128>>>(att, ids, out);
}

// round 10
// speedup vs baseline: 2.7327x; 1.1700x over previous
#include <cuda_runtime.h>
#include <cuda_bf16.h>

typedef unsigned long long u64;
typedef unsigned u32;

#define ND 20000
#define NG 20000
#define NC 10000
#define BB 4096

__device__ float g_E_drug[ND * 128];
__device__ float g_E_gene[NG * 128];
__device__ float g_E_cell[NC * 128];
__device__ float g_XW[6 * BB * 10 * 384];
__device__ float g_S[6 * BB * 128];
// transposed bf16-split weights [N][K]: [d | g | c | x(6) | u(6)]
#define WOFF_D 0
#define WOFF_G 262144
#define WOFF_C 393216
#define WOFF_X 458752
#define WOFF_U 753664
__device__ __nv_bfloat16 g_WT_hi[1048576];
__device__ __nv_bfloat16 g_WT_lo[1048576];

// ---------------- scalar helpers ----------------
__device__ __forceinline__ float sigmf(float x) {
    return __fdividef(1.f, 1.f + __expf(-x));
}
__device__ __forceinline__ float tanh_fast(float x) {
    float ax = fabsf(x);
    float e = __expf(-2.f * ax);
    return copysignf(__fdividef(1.f - e, 1.f + e), x);
}
// {lo=bf16_trunc(a_fp32bits), hi=bf16_trunc(b_fp32bits)}
__device__ __forceinline__ u32 hipack(u32 a, u32 b) {
    u32 d;
    asm("prmt.b32 %0, %1, %2, 0x7632;" : "=r"(d) : "r"(a), "r"(b));
    return d;
}
#define PACKBF2(r, a, b) \
    asm("cvt.rn.satfinite.bf16x2.f32 %0, %1, %2;" : "=r"(r) : "f"(b), "f"(a))

#define MMA_BF16(c, a0, a1, a2, a3, b0, b1) \
    asm volatile("mma.sync.aligned.m16n8k16.row.col.f32.bf16.bf16.f32 " \
        "{%0,%1,%2,%3}, {%4,%5,%6,%7}, {%8,%9}, {%0,%1,%2,%3};" \
        : "+f"((c)[0]), "+f"((c)[1]), "+f"((c)[2]), "+f"((c)[3]) \
        : "r"(a0), "r"(a1), "r"(a2), "r"(a3), "r"(b0), "r"(b1))

// ---------------- 0) transpose + split ALL weights (one launch) --------------
__global__ void wsplit_all(const float* __restrict__ Wd, const float* __restrict__ Wg,
                           const float* __restrict__ Wc, const float* __restrict__ gW,
                           const float* __restrict__ gU)
{
    int y = blockIdx.y;
    const float* src;
    int dstoff, K, N;
    if (y == 0)      { src = Wd; dstoff = WOFF_D; K = 2048; N = 128; }
    else if (y == 1) { src = Wg; dstoff = WOFF_G; K = 1024; N = 128; }
    else if (y == 2) { src = Wc; dstoff = WOFF_C; K = 512;  N = 128; }
    else if (y < 9)  { int lt = y - 3; src = gW + (size_t)lt * 49152;
                       dstoff = WOFF_X + lt * 49152; K = 128; N = 384; }
    else             { int lt = y - 9; src = gU + (size_t)lt * 49152;
                       dstoff = WOFF_U + lt * 49152; K = 128; N = 384; }
    __nv_bfloat16* hi = g_WT_hi + dstoff;
    __nv_bfloat16* lo = g_WT_lo + dstoff;
    int total = K * N;
    for (int i = blockIdx.x * blockDim.x + threadIdx.x; i < total; i += gridDim.x * blockDim.x) {
        int k = i / N, n = i - k * N;
        float w = src[i];
        u32 u = __float_as_uint(w);
        __nv_bfloat16_raw hr; hr.x = (unsigned short)(u >> 16);
        hi[(size_t)n * K + k] = __nv_bfloat16(hr);
        lo[(size_t)n * K + k] = __float2bfloat16(w - __uint_as_float(u & 0xffff0000u));
    }
}

// ---------------- 1) proj: all 3 tables in ONE grid --------------------------
__global__ __launch_bounds__(256, 2) void proj_mma(
    const float* __restrict__ drug, const float* __restrict__ gene,
    const float* __restrict__ cell,
    const float* __restrict__ bd, const float* __restrict__ bg,
    const float* __restrict__ bc)
{
    extern __shared__ u32 sm32[];
    u32* sAh = sm32;               // 128*36
    u32* sAl = sAh + 4608;
    u32* sBh = sAl + 4608;
    u32* sBl = sBh + 4608;

    int bx = blockIdx.x;
    const float *F, *bias;
    float* E;
    int N, K, woff, bstart;
    if (bx < 157)      { F = drug; bias = bd; E = g_E_drug; N = ND; K = 2048; woff = WOFF_D; bstart = bx; }
    else if (bx < 314) { F = gene; bias = bg; E = g_E_gene; N = NG; K = 1024; woff = WOFF_G; bstart = bx - 157; }
    else               { F = cell; bias = bc; E = g_E_cell; N = NC; K = 512;  woff = WOFF_C; bstart = bx - 314; }
    const __nv_bfloat16* WTh = g_WT_hi + woff;
    const __nv_bfloat16* WTl = g_WT_lo + woff;

    int tid = threadIdx.x, wm = tid >> 5, lane = tid & 31;
    int g = lane >> 2, t = lane & 3;
    int row0 = bstart * 128;

    float acc[16][4];
#pragma unroll
    for (int j = 0; j < 16; j++)
#pragma unroll
        for (int q = 0; q < 4; q++) acc[j][q] = 0.f;

    int srow = tid >> 1, skh = (tid & 1) * 32;
    int aclamp = row0 + srow < N ? row0 + srow : N - 1;
    const float* Abase = F + (size_t)aclamp * K;

    for (int kc = 0; kc < K; kc += 64) {
        __syncthreads();
        {
            const float4* src = (const float4*)(Abase + kc + skh);
            u32* dh = sAh + srow * 36 + (skh >> 1);
            u32* dl = sAl + srow * 36 + (skh >> 1);
#pragma unroll
            for (int i = 0; i < 8; i++) {
                float4 f = src[i];
                u32 ux = __float_as_uint(f.x), uy = __float_as_uint(f.y);
                u32 uz = __float_as_uint(f.z), uw = __float_as_uint(f.w);
                dh[i * 2]     = hipack(ux, uy);
                dh[i * 2 + 1] = hipack(uz, uw);
                float lx = f.x - __uint_as_float(ux & 0xffff0000u);
                float ly = f.y - __uint_as_float(uy & 0xffff0000u);
                float lz = f.z - __uint_as_float(uz & 0xffff0000u);
                float lw = f.w - __uint_as_float(uw & 0xffff0000u);
                u32 l0, l1;
                PACKBF2(l0, lx, ly);
                PACKBF2(l1, lz, lw);
                dl[i * 2] = l0; dl[i * 2 + 1] = l1;
            }
        }
        {
            const uint4* bh = (const uint4*)(WTh + (size_t)srow * K + kc + skh);
            const uint4* bl = (const uint4*)(WTl + (size_t)srow * K + kc + skh);
            uint4* dh = (uint4*)(sBh + srow * 36 + (skh >> 1));
            uint4* dl = (uint4*)(sBl + srow * 36 + (skh >> 1));
#pragma unroll
            for (int i = 0; i < 4; i++) { dh[i] = bh[i]; dl[i] = bl[i]; }
        }
        __syncthreads();

#pragma unroll
        for (int ks = 0; ks < 4; ks++) {
            int ab = (wm * 16 + g) * 36 + ks * 8 + t;
            u32 ah0 = sAh[ab],       ah1 = sAh[ab + 288];
            u32 ah2 = sAh[ab + 4],   ah3 = sAh[ab + 292];
            u32 al0 = sAl[ab],       al1 = sAl[ab + 288];
            u32 al2 = sAl[ab + 4],   al3 = sAl[ab + 292];
#pragma unroll
            for (int j = 0; j < 16; j++) {
                int bb = (j * 8 + g) * 36 + ks * 8 + t;
                u32 bh0 = sBh[bb], bh1 = sBh[bb + 4];
                u32 bl0 = sBl[bb], bl1 = sBl[bb + 4];
                MMA_BF16(acc[j], ah0, ah1, ah2, ah3, bh0, bh1);
                MMA_BF16(acc[j], al0, al1, al2, al3, bh0, bh1);
                MMA_BF16(acc[j], ah0, ah1, ah2, ah3, bl0, bl1);
            }
        }
    }

    int r0 = row0 + wm * 16 + g;
#pragma unroll
    for (int j = 0; j < 16; j++) {
        int col = j * 8 + 2 * t;
        float bx2 = bias[col], by = bias[col + 1];
        if (r0 < N)
            *(float2*)(E + (size_t)r0 * 128 + col) =
                make_float2(acc[j][0] + bx2, acc[j][1] + by);
        if (r0 + 8 < N)
            *(float2*)(E + (size_t)(r0 + 8) * 128 + col) =
                make_float2(acc[j][2] + bx2, acc[j][3] + by);
    }
}

// ---------------- 2) xw (unchanged, passing) ---------------------------------
__global__ __launch_bounds__(256, 2) void xw_mma(
    const float* __restrict__ gruB,
    const int* __restrict__ nd, const int* __restrict__ ng,
    const int* __restrict__ pnc)
{
    extern __shared__ u32 sm32[];
    u32* sAh = sm32;               // 128*68
    u32* sAl = sAh + 8704;
    u32* sBh = sAl + 8704;         // 64*68
    u32* sBl = sBh + 4352;

    int tid = threadIdx.x, wm = tid >> 5, lane = tid & 31;
    int g = lane >> 2, t = lane & 3;
    int lt = blockIdx.y, t3 = lt % 3;
    const int* nbr = (t3 == 0) ? nd : (t3 == 1) ? ng : pnc;
    const float* Etab = (t3 == 0) ? g_E_drug : (t3 == 1) ? g_E_gene : g_E_cell;
    const __nv_bfloat16* WTh = g_WT_hi + WOFF_X + lt * 49152;
    const __nv_bfloat16* WTl = g_WT_lo + WOFF_X + lt * 49152;
    const float* bias = gruB + lt * 384;
    float* out = g_XW + (size_t)lt * 40960 * 384;
    int row0 = blockIdx.x * 128;

    {
        int srow = tid >> 1, skh = (tid & 1) * 64;
        int id = nbr[row0 + srow];
        bool v = (id >= 0);
        const float4* src = (const float4*)(Etab + (size_t)(v ? id : 0) * 128 + skh);
        u32* dh = sAh + srow * 68 + (skh >> 1);
        u32* dl = sAl + srow * 68 + (skh >> 1);
#pragma unroll
        for (int i = 0; i < 16; i++) {
            float4 f = v ? src[i] : make_float4(0.f, 0.f, 0.f, 0.f);
            u32 ux = __float_as_uint(f.x), uy = __float_as_uint(f.y);
            u32 uz = __float_as_uint(f.z), uw = __float_as_uint(f.w);
            dh[i * 2]     = hipack(ux, uy);
            dh[i * 2 + 1] = hipack(uz, uw);
            float lx = f.x - __uint_as_float(ux & 0xffff0000u);
            float ly = f.y - __uint_as_float(uy & 0xffff0000u);
            float lz = f.z - __uint_as_float(uz & 0xffff0000u);
            float lw = f.w - __uint_as_float(uw & 0xffff0000u);
            u32 l0, l1;
            PACKBF2(l0, lx, ly);
            PACKBF2(l1, lz, lw);
            dl[i * 2] = l0; dl[i * 2 + 1] = l1;
        }
    }

    for (int ncb = 0; ncb < 6; ncb++) {
        __syncthreads();
        {
            int brow = tid >> 2, kq = (tid & 3) * 32;
            const uint4* bh = (const uint4*)(WTh + (size_t)(ncb * 64 + brow) * 128 + kq);
            const uint4* bl = (const uint4*)(WTl + (size_t)(ncb * 64 + brow) * 128 + kq);
            uint4* dh = (uint4*)(sBh + brow * 68 + (kq >> 1));
            uint4* dl = (uint4*)(sBl + brow * 68 + (kq >> 1));
#pragma unroll
            for (int i = 0; i < 4; i++) { dh[i] = bh[i]; dl[i] = bl[i]; }
        }
        __syncthreads();

        float acc[8][4];
#pragma unroll
        for (int j = 0; j < 8; j++)
#pragma unroll
            for (int q = 0; q < 4; q++) acc[j][q] = 0.f;

#pragma unroll
        for (int ks = 0; ks < 8; ks++) {
            int ab = (wm * 16 + g) * 68 + ks * 8 + t;
            u32 ah0 = sAh[ab],     ah1 = sAh[ab + 544];
            u32 ah2 = sAh[ab + 4], ah3 = sAh[ab + 548];
            u32 al0 = sAl[ab],     al1 = sAl[ab + 544];
            u32 al2 = sAl[ab + 4], al3 = sAl[ab + 548];
#pragma unroll
            for (int j = 0; j < 8; j++) {
                int bb = (j * 8 + g) * 68 + ks * 8 + t;
                u32 bh0 = sBh[bb], bh1 = sBh[bb + 4];
                u32 bl0 = sBl[bb], bl1 = sBl[bb + 4];
                MMA_BF16(acc[j], ah0, ah1, ah2, ah3, bh0, bh1);
                MMA_BF16(acc[j], al0, al1, al2, al3, bh0, bh1);
                MMA_BF16(acc[j], ah0, ah1, ah2, ah3, bl0, bl1);
            }
        }

        int r0 = row0 + wm * 16 + g;
#pragma unroll
        for (int j = 0; j < 8; j++) {
            int col = ncb * 64 + j * 8 + 2 * t;
            float bx = bias[col], by = bias[col + 1];
            *(float2*)(out + (size_t)r0 * 384 + col) =
                make_float2(acc[j][0] + bx, acc[j][1] + by);
            *(float2*)(out + (size_t)(r0 + 8) * 384 + col) =
                make_float2(acc[j][2] + bx, acc[j][3] + by);
        }
    }
}

// ---------------- 3) GRU recurrence via mma.sync — 512 thr (16 warps) --------
// Warp wm owns 8 cols [8wm, 8wm+8): z tile wm, r tile wm+16, n tile wm+32.
// Per warp per step: 2 mi x 3 j x 8 ks x 3 combos = 144 mma.
__global__ __launch_bounds__(512, 1) void gru_mma(
    const int* __restrict__ nd, const int* __restrict__ ng,
    const int* __restrict__ pnc)
{
    extern __shared__ u32 sg[];
    u32* sBh = sg;                  // 384*64 (U hi, XOR-swizzled)
    u32* sBl = sBh + 24576;
    u32* sAh = sBl + 24576;         // 32*68 (H hi)
    u32* sAl = sAh + 2176;
    float* sM = (float*)(sAl + 2176);   // 320
    float* sCnt = sM + 320;             // 32

    int tid = threadIdx.x, wm = tid >> 5, lane = tid & 31;
    int g = lane >> 2, t = lane & 3;
    int lt = blockIdx.y, t3 = lt % 3;
    const int* nbr = (t3 == 0) ? nd : (t3 == 1) ? ng : pnc;
    int b0 = blockIdx.x * 32;
    const u32* UTh = (const u32*)(g_WT_hi + WOFF_U + lt * 49152);
    const u32* UTl = (const u32*)(g_WT_lo + WOFF_U + lt * 49152);

    // stage U^T hi/lo with XOR swizzle (row n, u32 x -> x ^ ((n&7)<<2))
    for (int i = tid; i < 6144; i += 512) {
        int n = i >> 4;
        int xi = (i & 15) << 2;
        u32 dst = n * 64 + (xi ^ ((n & 7) << 2));
        *(uint4*)(sBh + dst) = *(const uint4*)(UTh + n * 64 + xi);
        *(uint4*)(sBl + dst) = *(const uint4*)(UTl + n * 64 + xi);
    }
    for (int i = tid; i < 320; i += 512) {
        int rr = i / 10, s = i % 10;
        sM[i] = (nbr[(size_t)(b0 + rr) * 10 + s] >= 0) ? 1.f : 0.f;
    }
    for (int i = tid; i < 2176; i += 512) { sAh[i] = 0u; sAl[i] = 0u; }
    __syncthreads();
    if (tid < 32) {
        float c = 0.f;
        for (int s = 0; s < 10; s++) c += sM[tid * 10 + s];
        sCnt[tid] = fmaxf(c, 1.f);
    }
    __syncthreads();

    float hreg[2][4], msum[2][4];
#pragma unroll
    for (int mi = 0; mi < 2; mi++)
#pragma unroll
        for (int q = 0; q < 4; q++) { hreg[mi][q] = 0.f; msum[mi][q] = 0.f; }

    for (int s = 0; s < 10; s++) {
        // gate inputs for this step: cols 8wm+2t, 8wm+2t+1 for rows (mi,g,rh)
        float2 xz[2][2], xr[2][2], xn[2][2];
        int d0 = 8 * wm + 2 * t;
#pragma unroll
        for (int mi = 0; mi < 2; mi++)
#pragma unroll
            for (int rh = 0; rh < 2; rh++) {
                int lrow = mi * 16 + g + rh * 8;
                const float* xwb = g_XW +
                    ((size_t)lt * 40960 + (size_t)(b0 + lrow) * 10 + s) * 384;
                xz[mi][rh] = *(const float2*)(xwb + d0);
                xr[mi][rh] = *(const float2*)(xwb + 128 + d0);
                xn[mi][rh] = *(const float2*)(xwb + 256 + d0);
            }

        float acc[2][3][4];
#pragma unroll
        for (int mi = 0; mi < 2; mi++)
#pragma unroll
            for (int j = 0; j < 3; j++)
#pragma unroll
                for (int q = 0; q < 4; q++) acc[mi][j][q] = 0.f;

#pragma unroll
        for (int ks = 0; ks < 8; ks++) {
            u32 ah[2][4], al[2][4];
#pragma unroll
            for (int mi = 0; mi < 2; mi++) {
                int ab = (mi * 16 + g) * 68 + ks * 8 + t;
                ah[mi][0] = sAh[ab];     ah[mi][1] = sAh[ab + 544];
                ah[mi][2] = sAh[ab + 4]; ah[mi][3] = sAh[ab + 548];
                al[mi][0] = sAl[ab];     al[mi][1] = sAl[ab + 544];
                al[mi][2] = sAl[ab + 4]; al[mi][3] = sAl[ab + 548];
            }
#pragma unroll
            for (int j = 0; j < 3; j++) {
                int n8 = j * 16 + wm;          // z: wm, r: wm+16, n: wm+32
                int nrow = n8 * 8 + g;
                u32 sw = (u32)((nrow & 7) << 2);
                u32 base = (u32)nrow * 64;
                u32 x0 = ((u32)(ks * 8 + t)) ^ sw;
                u32 x1 = ((u32)(ks * 8 + t + 4)) ^ sw;
                u32 bh0 = sBh[base + x0], bh1 = sBh[base + x1];
                u32 bl0 = sBl[base + x0], bl1 = sBl[base + x1];
#pragma unroll
                for (int mi = 0; mi < 2; mi++) {
                    MMA_BF16(acc[mi][j], ah[mi][0], ah[mi][1], ah[mi][2], ah[mi][3], bh0, bh1);
                    MMA_BF16(acc[mi][j], al[mi][0], al[mi][1], al[mi][2], al[mi][3], bh0, bh1);
                    MMA_BF16(acc[mi][j], ah[mi][0], ah[mi][1], ah[mi][2], ah[mi][3], bl0, bl1);
                }
            }
        }
        __syncthreads();   // all A (H) reads done before H update

#pragma unroll
        for (int mi = 0; mi < 2; mi++)
#pragma unroll
            for (int rh = 0; rh < 2; rh++) {
                int q0 = rh * 2;
                int lrow = mi * 16 + g + rh * 8;
                float2 vz = xz[mi][rh], vr = xr[mi][rh], vn = xn[mi][rh];
                float z0 = sigmf(vz.x + acc[mi][0][q0]);
                float z1 = sigmf(vz.y + acc[mi][0][q0 + 1]);
                float r0 = sigmf(vr.x + acc[mi][1][q0]);
                float r1 = sigmf(vr.y + acc[mi][1][q0 + 1]);
                float n0 = tanh_fast(vn.x + r0 * acc[mi][2][q0]);
                float n1 = tanh_fast(vn.y + r1 * acc[mi][2][q0 + 1]);
                float h0 = (1.f - z0) * n0 + z0 * hreg[mi][q0];
                float h1 = (1.f - z1) * n1 + z1 * hreg[mi][q0 + 1];
                hreg[mi][q0] = h0;
                hreg[mi][q0 + 1] = h1;
                float mk = sM[lrow * 10 + s];
                msum[mi][q0]     += mk * h0;
                msum[mi][q0 + 1] += mk * h1;
                u32 u0 = __float_as_uint(h0), u1 = __float_as_uint(h1);
                u32 hi = hipack(u0, u1);
                float l0f = h0 - __uint_as_float(u0 & 0xffff0000u);
                float l1f = h1 - __uint_as_float(u1 & 0xffff0000u);
                u32 lo;
                PACKBF2(lo, l0f, l1f);
                int hidx = lrow * 68 + wm * 4 + t;
                sAh[hidx] = hi;
                sAl[hidx] = lo;
            }
        __syncthreads();   // H fully updated before next step's A loads
    }

    // write S = msum / cnt
    int d0 = 8 * wm + 2 * t;
#pragma unroll
    for (int mi = 0; mi < 2; mi++)
#pragma unroll
        for (int rh = 0; rh < 2; rh++) {
            int q0 = rh * 2;
            int lrow = mi * 16 + g + rh * 8;
            float invc = 1.f / sCnt[lrow];
            *(float2*)(g_S + ((size_t)lt * BB + b0 + lrow) * 128 + d0) =
                make_float2(msum[mi][q0] * invc, msum[mi][q0 + 1] * invc);
        }
}

// ---------------- 4) attention combine ----------------
__device__ __forceinline__ float blkred(float v, float* red) {
    int d = threadIdx.x;
    red[d] = v;
    __syncthreads();
#pragma unroll
    for (int st = 64; st > 0; st >>= 1) {
        if (d < st) red[d] += red[d + st];
        __syncthreads();
    }
    float r = red[0];
    __syncthreads();
    return r;
}

__global__ __launch_bounds__(128) void final_kernel(
    const float* __restrict__ att, const int* __restrict__ ids,
    float* __restrict__ out)
{
    __shared__ float red[128];
    __shared__ float sC[3][128];
    int b = blockIdx.x, d = threadIdx.x;
    float h = g_E_drug[(size_t)ids[b] * 128 + d];
#pragma unroll
    for (int l = 0; l < 2; l++) {
        for (int t = 0; t < 3; t++)
            sC[t][d] = g_S[((size_t)(l * 3 + t) * BB + b) * 128 + d];
        __syncthreads();
        float a1 = att[l * 256 + d], a2 = att[l * 256 + 128 + d];
        float dh1 = blkred(h * a1, red);
        float dh2 = blkred(h * a2, red);
        float e0 = dh1 + dh2;
        float e1 = dh1 + blkred(sC[0][d] * a2, red);
        float e2 = dh1 + blkred(sC[1][d] * a2, red);
        float e3 = dh1 + blkred(sC[2][d] * a2, red);
        e0 = e0 > 0.f ? e0 : 0.01f * e0;
        e1 = e1 > 0.f ? e1 : 0.01f * e1;
        e2 = e2 > 0.f ? e2 : 0.01f * e2;
        e3 = e3 > 0.f ? e3 : 0.01f * e3;
        float mx = fmaxf(fmaxf(e0, e1), fmaxf(e2, e3));
        float w0 = __expf(e0 - mx), w1 = __expf(e1 - mx);
        float w2 = __expf(e2 - mx), w3 = __expf(e3 - mx);
        float inv = __fdividef(1.f, w0 + w1 + w2 + w3);
        h = (w0 * h + w1 * sC[0][d] + w2 * sC[1][d] + w3 * sC[2][d]) * inv;
        __syncthreads();
    }
    out[(size_t)b * 128 + d] = h;
}

// ---------------- launch ----------------
extern "C" void kernel_launch(void* const* d_in, const int* in_sizes, int n_in,
                              void* d_out, int out_size)
{
    const float* drug = (const float*)d_in[0];
    const float* gene = (const float*)d_in[1];
    const float* cell = (const float*)d_in[2];
    const float* Wd = (const float*)d_in[3];
    const float* bd = (const float*)d_in[4];
    const float* Wg = (const float*)d_in[5];
    const float* bg = (const float*)d_in[6];
    const float* Wc = (const float*)d_in[7];
    const float* bc = (const float*)d_in[8];
    const float* gW = (const float*)d_in[9];
    const float* gU = (const float*)d_in[10];
    const float* gb = (const float*)d_in[11];
    const float* att = (const float*)d_in[12];
    const int* ids = (const int*)d_in[13];
    const int* nd = (const int*)d_in[14];
    const int* ng = (const int*)d_in[15];
    const int* nc = (const int*)d_in[16];
    float* out = (float*)d_out;

    const int PROJ_SMEM = 4 * 4608 * 4;                 // 73728
    const int XW_SMEM   = (2 * 8704 + 2 * 4352) * 4;    // 104448
    const int GRUM_SMEM = (2 * 24576 + 2 * 2176 + 352) * 4; // 215424
    cudaFuncSetAttribute(proj_mma, cudaFuncAttributeMaxDynamicSharedMemorySize, PROJ_SMEM);
    cudaFuncSetAttribute(xw_mma, cudaFuncAttributeMaxDynamicSharedMemorySize, XW_SMEM);
    cudaFuncSetAttribute(gru_mma, cudaFuncAttributeMaxDynamicSharedMemorySize, GRUM_SMEM);

    // 0) weight transpose + bf16 split (all, one launch)
    wsplit_all<<<dim3(32, 15), 256>>>(Wd, Wg, Wc, gW, gU);

    // 1) project all 3 tables (one grid)
    proj_mma<<<393, 256, PROJ_SMEM>>>(drug, gene, cell, bd, bg, bc);

    // 2) XW = gathered E @ gru_W + gru_b
    xw_mma<<<dim3(320, 6), 256, XW_SMEM>>>(gb, nd, ng, nc);

    // 3) GRU recurrence + masked mean (tensor cores, 16 warps)
    gru_mma<<<dim3(BB / 32, 6), 512, GRUM_SMEM>>>(nd, ng, nc);

    // 4) attention combine + output
    final_kernel<<<BB, 128>>>(att, ids, out);
}